// round 4
// baseline (speedup 1.0000x reference)
#include <cuda_runtime.h>
#include <cstdint>

#define BB 8
#define NN 262144
#define KK 256
#define DD 16
#define CAP 2048
#define MMAX 1024

// ---------------- scratch (device globals; no allocation) ----------------
__device__ float  g_sum_f [BB][KK];
__device__ int    g_cnt_cp[BB][KK];
__device__ int    g_inst  [BB][KK];
__device__ int    g_first [BB][KK];
__device__ float  g_sd2   [BB][KK];
__device__ float4 g_anchor[BB][KK][4];
__device__ int    g_Mv    [BB];
__device__ int    g_cplist[BB][CAP];
__device__ float  g_scal_f[BB][4];    // 0: sum ce0*~cp, 1: sum ce0*bg, 2: pos_margin num, 3: neg_margin num
__device__ int    g_scal_i[BB][2];    // 0: n_cp(all), 1: n_bg
__device__ float  g_rep   [BB];

// fast sigmoid + softplus: 2 MUFU (EX2, LG2) + FMA-pipe Newton reciprocal.
// Seed valid on u in [1,2]:  y0 = 24/17 - 8/17*u  (minimax, rel err 1/17).
// Two Newton steps -> rel err ~1.2e-5.
__device__ __forceinline__ void fast_sig_sp(float x, float& p, float& ce0) {
    const float t = __expf(-fabsf(x));         // (0,1]
    const float u = 1.f + t;                   // (1,2]
    float y = __fmaf_rn(u, -0.47058824f, 1.4117647f);
    y = y * __fmaf_rn(-u, y, 2.f);
    y = y * __fmaf_rn(-u, y, 2.f);
    ce0 = fmaxf(x, 0.f) + __logf(u);           // softplus(x)
    p   = (x >= 0.f) ? y : t * y;              // sigmoid(x)
}

// ---------------- init ----------------
__global__ void init_kernel() {
    int t = blockIdx.x * blockDim.x + threadIdx.x;
    if (t < BB * KK) {
        int b = t >> 8, k = t & 255;
        g_sum_f[b][k]  = 0.f;
        g_cnt_cp[b][k] = 0;
        g_inst[b][k]   = 0;
        g_first[b][k]  = NN;
        g_sd2[b][k]    = 0.f;
    }
    if (t < BB) {
        g_Mv[t]  = 0;
        g_rep[t] = 0.f;
        #pragma unroll
        for (int j = 0; j < 4; j++) g_scal_f[t][j] = 0.f;
        g_scal_i[t][0] = 0; g_scal_i[t][1] = 0;
    }
}

// ---------------- pass A: beta/sid/cp scan (2048 pts/block, grid 128x8) ----------------
__global__ void __launch_bounds__(256) pass_a_kernel(
    const float* __restrict__ beta,
    const int* __restrict__ sid,
    const int* __restrict__ cp)
{
    const int b   = blockIdx.y;
    const int tid = threadIdx.x;

    __shared__ float s_f[KK];
    __shared__ int   s_cnt[KK];
    __shared__ int   s_inst[KK];
    __shared__ int   s_first[KK];
    __shared__ float s_sc[4];
    __shared__ int   s_si[2];

    s_f[tid] = 0.f; s_cnt[tid] = 0; s_inst[tid] = 0; s_first[tid] = NN;
    if (tid < 4) s_sc[tid] = 0.f;
    if (tid < 2) s_si[tid] = 0;
    __syncthreads();

    float ce0n = 0.f, bg = 0.f, pm = 0.f, nm = 0.f;
    int ncp = 0, nbg = 0;

    const size_t ev_base = (size_t)b * NN;
    const int blk_base = blockIdx.x * 2048;

    #pragma unroll
    for (int it = 0; it < 2; it++) {
        const int li0 = blk_base + it * 1024 + tid * 4;
        const int4   s4 = *reinterpret_cast<const int4*>(sid + ev_base + li0);
        const int4   c4 = *reinterpret_cast<const int4*>(cp  + ev_base + li0);
        const float4 x4 = *reinterpret_cast<const float4*>(beta + ev_base + li0);

        const int   sv[4] = {s4.x, s4.y, s4.z, s4.w};
        const int   cv[4] = {c4.x, c4.y, c4.z, c4.w};
        const float xv[4] = {x4.x, x4.y, x4.z, x4.w};

        #pragma unroll
        for (int j = 0; j < 4; j++) {
            const int   s = sv[j];
            const float x = xv[j];
            float p, ce0;
            fast_sig_sp(x, p, ce0);

            if (cv[j]) {
                ncp++;
                pm += fmaxf(0.8f - p, 0.f);
                if (s >= 0) {
                    const float om = 1.f - p;
                    atomicAdd(&s_f[s], 0.75f * om * om * (ce0 - x));
                    atomicAdd(&s_cnt[s], 1);
                    atomicMin(&s_first[s], li0 + j);
                    int pos = atomicAdd(&g_Mv[b], 1);
                    if (pos < CAP) g_cplist[b][pos] = li0 + j;
                }
            } else {
                ce0n += ce0;
                nm += fmaxf(p - 0.2f, 0.f);
            }
            if (s == -1) { nbg++; bg += ce0; }
            else atomicAdd(&s_inst[s], 1);     // s >= 0 here (s in [-1,K))
        }
    }

    atomicAdd(&s_sc[0], ce0n);
    atomicAdd(&s_sc[1], bg);
    atomicAdd(&s_sc[2], pm);
    atomicAdd(&s_sc[3], nm);
    atomicAdd(&s_si[0], ncp);
    atomicAdd(&s_si[1], nbg);
    __syncthreads();

    if (s_f[tid] != 0.f)   atomicAdd(&g_sum_f[b][tid], s_f[tid]);
    if (s_cnt[tid])        atomicAdd(&g_cnt_cp[b][tid], s_cnt[tid]);
    if (s_inst[tid])       atomicAdd(&g_inst[b][tid], s_inst[tid]);
    if (s_first[tid] < NN) atomicMin(&g_first[b][tid], s_first[tid]);
    if (tid < 4) atomicAdd(&g_scal_f[b][tid], s_sc[tid]);
    if (tid < 2) atomicAdd(&g_scal_i[b][tid], s_si[tid]);
}

// ---------------- anchor gather ----------------
__global__ void gather_anchor_kernel(const float* __restrict__ embed) {
    int t = blockIdx.x * blockDim.x + threadIdx.x;   // BB*KK*4
    if (t >= BB * KK * 4) return;
    int q = t & 3;
    int k = (t >> 2) & (KK - 1);
    int b = t >> 10;
    int fi = g_first[b][k];
    float4 v = make_float4(0.f, 0.f, 0.f, 0.f);
    if (fi < NN)
        v = reinterpret_cast<const float4*>(embed + ((size_t)b * NN + fi) * DD)[q];
    g_anchor[b][k][q] = v;
}

// ---------------- pass B: attraction (2048 pts/block, 512 thr, grid 128x8) --------------
__global__ void __launch_bounds__(512) pass_b_kernel(
    const float* __restrict__ embed,
    const int* __restrict__ sid)
{
    const int b   = blockIdx.y;
    const int tid = threadIdx.x;

    __shared__ float4        sA[KK][4];
    __shared__ float         sd2[KK];
    __shared__ unsigned char shc[KK];

    #pragma unroll
    for (int i = tid; i < KK * 4; i += 512)
        sA[i >> 2][i & 3] = g_anchor[b][i >> 2][i & 3];
    if (tid < KK) {
        sd2[tid] = 0.f;
        shc[tid] = (g_cnt_cp[b][tid] > 0) ? 1 : 0;
    }
    __syncthreads();

    const size_t ev_base = (size_t)b * NN;
    const int li0 = blockIdx.x * 2048 + tid * 4;
    const int4 s4 = *reinterpret_cast<const int4*>(sid + ev_base + li0);
    const int sv[4] = {s4.x, s4.y, s4.z, s4.w};

    #pragma unroll
    for (int j = 0; j < 4; j++) {
        const int s = sv[j];
        if (s >= 0 && shc[s]) {
            const float4* e = reinterpret_cast<const float4*>(embed + (ev_base + li0 + j) * DD);
            float d2 = 0.f;
            #pragma unroll
            for (int q = 0; q < 4; q++) {
                float4 ev = e[q];
                float4 av = sA[s][q];
                float dx = ev.x - av.x, dy = ev.y - av.y;
                float dz = ev.z - av.z, dw = ev.w - av.w;
                d2 += dx * dx + dy * dy + dz * dz + dw * dw;
            }
            atomicAdd(&sd2[s], d2);
        }
    }
    __syncthreads();
    if (tid < KK && sd2[tid] != 0.f) atomicAdd(&g_sd2[b][tid], sd2[tid]);
}

// ---------------- repulsion ----------------
__global__ void __launch_bounds__(1024) repulsion_kernel(const float* __restrict__ embed) {
    const int b   = blockIdx.x;
    const int tid = threadIdx.x;

    __shared__ int   sidx[CAP];
    __shared__ float ej[256 * DD];
    __shared__ float red[32];

    const int Mv   = g_Mv[b];
    const int mcol = min(Mv, CAP);
    for (int i = tid; i < CAP; i += 1024)
        sidx[i] = (i < mcol) ? g_cplist[b][i] : 0x7fffffff;
    __syncthreads();

    const int msel = min(Mv, MMAX);
    if (Mv > MMAX) {
        for (int ksz = 2; ksz <= CAP; ksz <<= 1) {
            for (int j = ksz >> 1; j > 0; j >>= 1) {
                for (int i = tid; i < CAP; i += 1024) {
                    int ixj = i ^ j;
                    if (ixj > i) {
                        bool up = ((i & ksz) == 0);
                        int a = sidx[i], c = sidx[ixj];
                        if ((a > c) == up) { sidx[i] = c; sidx[ixj] = a; }
                    }
                }
                __syncthreads();
            }
        }
    }

    const bool act = (tid < msel);
    float myE[DD];
    if (act) {
        const float* e = embed + ((size_t)b * NN + sidx[tid]) * DD;
        #pragma unroll
        for (int d = 0; d < DD; d++) myE[d] = e[d];
    }

    float acc = 0.f;
    for (int j0 = 0; j0 < msel; j0 += 256) {
        const int cnt = min(256, msel - j0);
        __syncthreads();
        for (int i = tid; i < cnt * DD; i += 1024) {
            int jj = i >> 4, dd = i & 15;
            ej[i] = embed[((size_t)b * NN + sidx[j0 + jj]) * DD + dd];
        }
        __syncthreads();
        if (act) {
            for (int j = 0; j < cnt; j++) {
                float d2 = 0.f;
                #pragma unroll
                for (int d = 0; d < DD; d++) {
                    float df = myE[d] - ej[j * DD + d];
                    d2 += df * df;
                }
                acc += __expf(-d2);
            }
        }
    }

    #pragma unroll
    for (int off = 16; off; off >>= 1) acc += __shfl_down_sync(0xffffffff, acc, off);
    if ((tid & 31) == 0) red[tid >> 5] = acc;
    __syncthreads();
    if (tid == 0) {
        float tot = 0.f;
        for (int w = 0; w < 32; w++) tot += red[w];
        float fM = (float)Mv;
        g_rep[b] = (Mv > 1) ? tot / fmaxf(fM * fM, 1.f) : 0.f;
    }
}

// ---------------- finalize ----------------
__global__ void __launch_bounds__(256) finalize_kernel(float* __restrict__ out) {
    const int tid  = threadIdx.x;
    const int lane = tid & 31;
    const int wid  = tid >> 5;
    __shared__ float rw[8], rwf[8], rat[8];
    __shared__ float s_total[1], s_cnt[1];
    if (tid == 0) { s_total[0] = 0.f; s_cnt[0] = 0.f; }
    __syncthreads();

    for (int b = 0; b < BB; b++) {
        const int c    = g_cnt_cp[b][tid];
        const int inst = g_inst[b][tid];
        float w = 0.f, wf = 0.f, at = 0.f;
        if (c > 0) {
            w  = (float)inst;
            wf = w * g_sum_f[b][tid] / fmaxf((float)c, 1.f);
            at = g_sd2[b][tid] / fmaxf((float)inst, 1.f);
        }
        #pragma unroll
        for (int off = 16; off; off >>= 1) {
            w  += __shfl_down_sync(0xffffffff, w,  off);
            wf += __shfl_down_sync(0xffffffff, wf, off);
            at += __shfl_down_sync(0xffffffff, at, off);
        }
        if (lane == 0) { rw[wid] = w; rwf[wid] = wf; rat[wid] = at; }
        __syncthreads();
        if (tid == 0) {
            float sw = 0.f, swf = 0.f, sat = 0.f;
            for (int q = 0; q < 8; q++) { sw += rw[q]; swf += rwf[q]; sat += rat[q]; }
            const float pos_bce = swf / fmaxf(sw, 1.f);

            const float n_cp  = (float)g_scal_i[b][0];
            const float n_bg  = (float)g_scal_i[b][1];
            const float n_ncp = (float)NN - n_cp;
            const float n_val = (float)NN - n_bg;

            const float neg_bce    = (n_ncp > 0.f) ? g_scal_f[b][0] / fmaxf(n_ncp, 1.f) : 0.f;
            const float bg_bce     = (n_bg  > 0.f) ? g_scal_f[b][1] / fmaxf(n_bg,  1.f) : 0.f;
            const float pos_margin = g_scal_f[b][2] / fmaxf(n_cp, 1.f);
            const float neg_margin = (n_ncp > 0.f) ? g_scal_f[b][3] / fmaxf(n_ncp, 1.f) : 0.f;

            const float beta_loss = 10.f * pos_bce + 3.f * neg_bce + 6.f * bg_bce
                                  + 10.f * (pos_margin + neg_margin);
            const float loss = beta_loss + sat + g_rep[b];

            const bool ok = (n_val > 0.f) && (g_Mv[b] > 0);
            if (ok) { s_total[0] += loss; s_cnt[0] += 1.f; }
        }
        __syncthreads();
    }
    if (tid == 0)
        out[0] = (s_cnt[0] > 0.f) ? s_total[0] / fmaxf(s_cnt[0], 1.f) : 0.f;
}

// ---------------- launch ----------------
extern "C" void kernel_launch(void* const* d_in, const int* in_sizes, int n_in,
                              void* d_out, int out_size)
{
    (void)in_sizes; (void)n_in; (void)out_size;
    const float* beta  = (const float*)d_in[0];
    const float* embed = (const float*)d_in[1];
    const int*   sid   = (const int*)d_in[2];
    const int*   cp    = (const int*)d_in[3];

    init_kernel<<<8, 256>>>();
    pass_a_kernel<<<dim3(128, BB), 256>>>(beta, sid, cp);
    gather_anchor_kernel<<<32, 256>>>(embed);
    pass_b_kernel<<<dim3(128, BB), 512>>>(embed, sid);
    repulsion_kernel<<<BB, 1024>>>(embed);
    finalize_kernel<<<1, 256>>>((float*)d_out);
}

// round 6
// speedup vs baseline: 1.4209x; 1.4209x over previous
#include <cuda_runtime.h>
#include <cstdint>

#define BB 8
#define NN 262144
#define KK 256
#define DD 16
#define CAP 2048
#define MMAX 1024

// ---------------- scratch (device globals; no allocation) ----------------
__device__ float  g_sum_f [BB][KK];
__device__ int    g_cnt_cp[BB][KK];
__device__ int    g_inst  [BB][KK];
__device__ int    g_first [BB][KK];
__device__ float  g_sd2   [BB][KK];
__device__ float4 g_anchor[BB][KK][4];
__device__ int    g_Mv    [BB];
__device__ int    g_cplist[BB][CAP];
__device__ float  g_scal_f[BB][4];    // 0: sum ce0*~cp, 1: sum ce0*bg, 2: pos_margin num, 3: neg_margin num
__device__ int    g_scal_i[BB][2];    // 0: n_cp(all), 1: n_bg
__device__ float  g_rep   [BB];       // UNNORMALIZED sum of exp(-d2) over selected pairs
__device__ float4 g_cpemb [BB][MMAX * 4];  // compact CP embeddings (msel rows x 4 float4)

// fast sigmoid + softplus: 2 MUFU (EX2, LG2) + FMA-pipe Newton reciprocal.
// Seed valid on u in (1,2]:  y0 = 24/17 - 8/17*u  (minimax, rel err 1/17).
// Two Newton steps -> rel err ~1.2e-5.
__device__ __forceinline__ void fast_sig_sp(float x, float& p, float& ce0) {
    const float t = __expf(-fabsf(x));         // (0,1]
    const float u = 1.f + t;                   // (1,2]
    float y = __fmaf_rn(u, -0.47058824f, 1.4117647f);
    y = y * __fmaf_rn(-u, y, 2.f);
    y = y * __fmaf_rn(-u, y, 2.f);
    ce0 = fmaxf(x, 0.f) + __logf(u);           // softplus(x)
    p   = (x >= 0.f) ? y : t * y;              // sigmoid(x)
}

// ---------------- init ----------------
__global__ void init_kernel() {
    int t = blockIdx.x * blockDim.x + threadIdx.x;
    if (t < BB * KK) {
        int b = t >> 8, k = t & 255;
        g_sum_f[b][k]  = 0.f;
        g_cnt_cp[b][k] = 0;
        g_inst[b][k]   = 0;
        g_first[b][k]  = NN;
        g_sd2[b][k]    = 0.f;
    }
    if (t < BB) {
        g_Mv[t]  = 0;
        g_rep[t] = 0.f;
        #pragma unroll
        for (int j = 0; j < 4; j++) g_scal_f[t][j] = 0.f;
        g_scal_i[t][0] = 0; g_scal_i[t][1] = 0;
    }
}

// ---------------- pass A: beta/sid/cp scan (4096 pts/block, grid 64x8) ----------------
__global__ void __launch_bounds__(256) pass_a_kernel(
    const float* __restrict__ beta,
    const int* __restrict__ sid,
    const int* __restrict__ cp)
{
    const int b   = blockIdx.y;
    const int tid = threadIdx.x;

    __shared__ float s_f[KK];
    __shared__ int   s_cnt[KK];
    __shared__ int   s_inst[KK];
    __shared__ int   s_first[KK];
    __shared__ float s_sc[4];
    __shared__ int   s_si[2];

    s_f[tid] = 0.f; s_cnt[tid] = 0; s_inst[tid] = 0; s_first[tid] = NN;
    if (tid < 4) s_sc[tid] = 0.f;
    if (tid < 2) s_si[tid] = 0;
    __syncthreads();

    float ce0n = 0.f, bg = 0.f, pm = 0.f, nm = 0.f;
    int ncp = 0, nbg = 0;

    const size_t ev_base = (size_t)b * NN;
    const int blk_base = blockIdx.x * 4096;

    for (int it = 0; it < 4; it++) {
        const int li0 = blk_base + it * 1024 + tid * 4;
        const int4   s4 = *reinterpret_cast<const int4*>(sid + ev_base + li0);
        const int4   c4 = *reinterpret_cast<const int4*>(cp  + ev_base + li0);
        const float4 x4 = *reinterpret_cast<const float4*>(beta + ev_base + li0);

        const int   sv[4] = {s4.x, s4.y, s4.z, s4.w};
        const int   cv[4] = {c4.x, c4.y, c4.z, c4.w};
        const float xv[4] = {x4.x, x4.y, x4.z, x4.w};

        #pragma unroll
        for (int j = 0; j < 4; j++) {
            const int   s = sv[j];
            const float x = xv[j];
            float p, ce0;
            fast_sig_sp(x, p, ce0);

            if (cv[j]) {
                ncp++;
                pm += fmaxf(0.8f - p, 0.f);
                if (s >= 0) {
                    const float om = 1.f - p;
                    atomicAdd(&s_f[s], 0.75f * om * om * (ce0 - x));
                    atomicAdd(&s_cnt[s], 1);
                    atomicMin(&s_first[s], li0 + j);
                    int pos = atomicAdd(&g_Mv[b], 1);
                    if (pos < CAP) g_cplist[b][pos] = li0 + j;
                }
            } else {
                ce0n += ce0;
                nm += fmaxf(p - 0.2f, 0.f);
            }
            if (s == -1) { nbg++; bg += ce0; }
            else atomicAdd(&s_inst[s], 1);     // s >= 0 here (s in [-1,K))
        }
    }

    atomicAdd(&s_sc[0], ce0n);
    atomicAdd(&s_sc[1], bg);
    atomicAdd(&s_sc[2], pm);
    atomicAdd(&s_sc[3], nm);
    atomicAdd(&s_si[0], ncp);
    atomicAdd(&s_si[1], nbg);
    __syncthreads();

    if (s_f[tid] != 0.f)   atomicAdd(&g_sum_f[b][tid], s_f[tid]);
    if (s_cnt[tid])        atomicAdd(&g_cnt_cp[b][tid], s_cnt[tid]);
    if (s_inst[tid])       atomicAdd(&g_inst[b][tid], s_inst[tid]);
    if (s_first[tid] < NN) atomicMin(&g_first[b][tid], s_first[tid]);
    if (tid < 4) atomicAdd(&g_scal_f[b][tid], s_sc[tid]);
    if (tid < 2) atomicAdd(&g_scal_i[b][tid], s_si[tid]);
}

// ---------------- anchor gather ----------------
__global__ void gather_anchor_kernel(const float* __restrict__ embed) {
    int t = blockIdx.x * blockDim.x + threadIdx.x;   // BB*KK*4
    if (t >= BB * KK * 4) return;
    int q = t & 3;
    int k = (t >> 2) & (KK - 1);
    int b = t >> 10;
    int fi = g_first[b][k];
    float4 v = make_float4(0.f, 0.f, 0.f, 0.f);
    if (fi < NN)
        v = reinterpret_cast<const float4*>(embed + ((size_t)b * NN + fi) * DD)[q];
    g_anchor[b][k][q] = v;
}

// ---------------- pass B: attraction, 4 lanes per row (coalesced) ----------------
// block 512 thr, grid (128, BB); block covers 2048 rows; warp handles 8 rows/iter.
// Shuffles use the 4-lane GROUP mask (branch is uniform within a group).
__global__ void __launch_bounds__(512) pass_b_kernel(
    const float* __restrict__ embed,
    const int* __restrict__ sid)
{
    const int b    = blockIdx.y;
    const int tid  = threadIdx.x;
    const int lane = tid & 31;
    const int wrp  = tid >> 5;          // 0..15
    const int g    = lane >> 2;         // row group within warp, 0..7
    const int q    = lane & 3;          // float4 slot within row
    const unsigned gmask = 0xFu << (lane & 28);   // this group's 4 lanes

    __shared__ float4        sA[KK][4];
    __shared__ float         sd2[KK];
    __shared__ unsigned char shc[KK];

    #pragma unroll
    for (int i = tid; i < KK * 4; i += 512)
        sA[i >> 2][i & 3] = g_anchor[b][i >> 2][i & 3];
    if (tid < KK) {
        sd2[tid] = 0.f;
        shc[tid] = (g_cnt_cp[b][tid] > 0) ? 1 : 0;
    }
    __syncthreads();

    const size_t ev_base = (size_t)b * NN;
    const int blk_base = blockIdx.x * 2048;

    #pragma unroll 4
    for (int it = 0; it < 16; it++) {
        const int row = blk_base + it * 128 + wrp * 8 + g;
        const int s = sid[ev_base + row];
        if (s >= 0 && shc[s]) {         // uniform across the 4-lane group
            const float4 ev = reinterpret_cast<const float4*>(embed + (ev_base + row) * DD)[q];
            const float4 av = sA[s][q];
            const float dx = ev.x - av.x, dy = ev.y - av.y;
            const float dz = ev.z - av.z, dw = ev.w - av.w;
            float d2 = dx * dx + dy * dy + dz * dz + dw * dw;
            d2 += __shfl_xor_sync(gmask, d2, 1);
            d2 += __shfl_xor_sync(gmask, d2, 2);
            if (q == 0) atomicAdd(&sd2[s], d2);
        }
    }
    __syncthreads();
    if (tid < KK && sd2[tid] != 0.f) atomicAdd(&g_sd2[b][tid], sd2[tid]);
}

// ---------------- repulsion prep: select (sort only if Mv>MMAX) + gather CP embeds ----
__global__ void __launch_bounds__(1024) rep_prep_kernel(const float* __restrict__ embed) {
    const int b   = blockIdx.x;
    const int tid = threadIdx.x;
    __shared__ int sidx[CAP];

    const int Mv   = g_Mv[b];
    const int mcol = min(Mv, CAP);
    const int msel = min(Mv, MMAX);

    for (int i = tid; i < CAP; i += 1024)
        sidx[i] = (i < mcol) ? g_cplist[b][i] : 0x7fffffff;
    __syncthreads();

    if (Mv > MMAX) {   // statistically never; correctness fallback
        for (int ksz = 2; ksz <= CAP; ksz <<= 1) {
            for (int j = ksz >> 1; j > 0; j >>= 1) {
                for (int i = tid; i < CAP; i += 1024) {
                    int ixj = i ^ j;
                    if (ixj > i) {
                        bool up = ((i & ksz) == 0);
                        int a = sidx[i], c = sidx[ixj];
                        if ((a > c) == up) { sidx[i] = c; sidx[ixj] = a; }
                    }
                }
                __syncthreads();
            }
        }
    }

    // gather selected CP embeddings into compact global buffer
    for (int t = tid; t < msel * 4; t += 1024) {
        const int i = t >> 2, qq = t & 3;
        g_cpemb[b][i * 4 + qq] =
            reinterpret_cast<const float4*>(embed + ((size_t)b * NN + sidx[i]) * DD)[qq];
    }
}

// ---------------- repulsion compute: grid (16 j-chunks, BB), 256 thr ----------------
#define RCH 64
__global__ void __launch_bounds__(256) rep_compute_kernel() {
    const int b   = blockIdx.y;
    const int tid = threadIdx.x;
    const int j0  = blockIdx.x * RCH;

    const int Mv   = g_Mv[b];
    const int msel = min(Mv, MMAX);
    if (j0 >= msel) return;
    const int cnt = min(RCH, msel - j0);

    __shared__ float sj[RCH * DD];   // 4 KB
    __shared__ float red[8];

    for (int t = tid; t < cnt * 4; t += 256) {
        const int j = t >> 2, qq = t & 3;
        reinterpret_cast<float4*>(sj)[j * 4 + qq] = g_cpemb[b][(j0 + j) * 4 + qq];
    }
    __syncthreads();

    float acc = 0.f;
    for (int i = tid; i < msel; i += 256) {
        float myE[DD];
        #pragma unroll
        for (int qq = 0; qq < 4; qq++) {
            const float4 v = g_cpemb[b][i * 4 + qq];
            myE[qq * 4 + 0] = v.x; myE[qq * 4 + 1] = v.y;
            myE[qq * 4 + 2] = v.z; myE[qq * 4 + 3] = v.w;
        }
        for (int j = 0; j < cnt; j++) {
            float d2 = 0.f;
            #pragma unroll
            for (int d = 0; d < DD; d++) {
                const float df = myE[d] - sj[j * DD + d];
                d2 = __fmaf_rn(df, df, d2);
            }
            acc += __expf(-d2);
        }
    }

    #pragma unroll
    for (int off = 16; off; off >>= 1) acc += __shfl_down_sync(0xffffffff, acc, off);
    if ((tid & 31) == 0) red[tid >> 5] = acc;
    __syncthreads();
    if (tid == 0) {
        float tot = 0.f;
        #pragma unroll
        for (int w = 0; w < 8; w++) tot += red[w];
        atomicAdd(&g_rep[b], tot);
    }
}

// ---------------- finalize ----------------
__global__ void __launch_bounds__(256) finalize_kernel(float* __restrict__ out) {
    const int tid  = threadIdx.x;
    const int lane = tid & 31;
    const int wid  = tid >> 5;
    __shared__ float rw[8], rwf[8], rat[8];
    __shared__ float s_total[1], s_cnt[1];
    if (tid == 0) { s_total[0] = 0.f; s_cnt[0] = 0.f; }
    __syncthreads();

    for (int b = 0; b < BB; b++) {
        const int c    = g_cnt_cp[b][tid];
        const int inst = g_inst[b][tid];
        float w = 0.f, wf = 0.f, at = 0.f;
        if (c > 0) {
            w  = (float)inst;
            wf = w * g_sum_f[b][tid] / fmaxf((float)c, 1.f);
            at = g_sd2[b][tid] / fmaxf((float)inst, 1.f);
        }
        #pragma unroll
        for (int off = 16; off; off >>= 1) {
            w  += __shfl_down_sync(0xffffffff, w,  off);
            wf += __shfl_down_sync(0xffffffff, wf, off);
            at += __shfl_down_sync(0xffffffff, at, off);
        }
        if (lane == 0) { rw[wid] = w; rwf[wid] = wf; rat[wid] = at; }
        __syncthreads();
        if (tid == 0) {
            float sw = 0.f, swf = 0.f, sat = 0.f;
            for (int qq = 0; qq < 8; qq++) { sw += rw[qq]; swf += rwf[qq]; sat += rat[qq]; }
            const float pos_bce = swf / fmaxf(sw, 1.f);

            const float n_cp  = (float)g_scal_i[b][0];
            const float n_bg  = (float)g_scal_i[b][1];
            const float n_ncp = (float)NN - n_cp;
            const float n_val = (float)NN - n_bg;

            const float neg_bce    = (n_ncp > 0.f) ? g_scal_f[b][0] / fmaxf(n_ncp, 1.f) : 0.f;
            const float bg_bce     = (n_bg  > 0.f) ? g_scal_f[b][1] / fmaxf(n_bg,  1.f) : 0.f;
            const float pos_margin = g_scal_f[b][2] / fmaxf(n_cp, 1.f);
            const float neg_margin = (n_ncp > 0.f) ? g_scal_f[b][3] / fmaxf(n_ncp, 1.f) : 0.f;

            const float beta_loss = 10.f * pos_bce + 3.f * neg_bce + 6.f * bg_bce
                                  + 10.f * (pos_margin + neg_margin);

            const int   Mv = g_Mv[b];
            const float fM = (float)Mv;
            const float rep_term = (Mv > 1) ? g_rep[b] / fmaxf(fM * fM, 1.f) : 0.f;

            const float loss = beta_loss + sat + rep_term;

            const bool ok = (n_val > 0.f) && (Mv > 0);
            if (ok) { s_total[0] += loss; s_cnt[0] += 1.f; }
        }
        __syncthreads();
    }
    if (tid == 0)
        out[0] = (s_cnt[0] > 0.f) ? s_total[0] / fmaxf(s_cnt[0], 1.f) : 0.f;
}

// ---------------- launch ----------------
extern "C" void kernel_launch(void* const* d_in, const int* in_sizes, int n_in,
                              void* d_out, int out_size)
{
    (void)in_sizes; (void)n_in; (void)out_size;
    const float* beta  = (const float*)d_in[0];
    const float* embed = (const float*)d_in[1];
    const int*   sid   = (const int*)d_in[2];
    const int*   cp    = (const int*)d_in[3];

    init_kernel<<<8, 256>>>();
    pass_a_kernel<<<dim3(64, BB), 256>>>(beta, sid, cp);
    gather_anchor_kernel<<<32, 256>>>(embed);
    pass_b_kernel<<<dim3(128, BB), 512>>>(embed, sid);
    rep_prep_kernel<<<BB, 1024>>>(embed);
    rep_compute_kernel<<<dim3(16, BB), 256>>>();
    finalize_kernel<<<1, 256>>>((float*)d_out);
}

// round 7
// speedup vs baseline: 1.4583x; 1.0264x over previous
#include <cuda_runtime.h>
#include <cstdint>

#define BB 8
#define NN 262144
#define KK 256
#define DD 16
#define CAP 2048
#define MMAX 1024

// ---------------- scratch (device globals; zero-init == reset state) ----------------
__device__ float  g_sum_f [BB][KK];
__device__ int    g_cnt_cp[BB][KK];
__device__ int    g_inst  [BB][KK];
__device__ int    g_first [BB][KK];   // stores max(NN - li); 0 == no CP
__device__ float  g_sd2   [BB][KK];
__device__ float4 g_anchor[BB][KK][4];
__device__ int    g_Mv    [BB];
__device__ int    g_cplist[BB][CAP];
__device__ float  g_scal_f[BB][4];    // 0: sum ce0*~cp, 1: sum ce0*bg, 2: pos_margin, 3: neg_margin
__device__ int    g_scal_i[BB][2];    // 0: n_cp(all), 1: n_bg
__device__ float  g_rep   [BB];
__device__ float4 g_cpemb [BB][MMAX * 4];

// fast sigmoid + softplus: 2 MUFU + FMA-pipe Newton rcp (seed valid on u in (1,2])
__device__ __forceinline__ void fast_sig_sp(float x, float& p, float& ce0) {
    const float t = __expf(-fabsf(x));
    const float u = 1.f + t;
    float y = __fmaf_rn(u, -0.47058824f, 1.4117647f);
    y = y * __fmaf_rn(-u, y, 2.f);
    y = y * __fmaf_rn(-u, y, 2.f);
    ce0 = fmaxf(x, 0.f) + __logf(u);
    p   = (x >= 0.f) ? y : t * y;
}

// ---------------- pass A: beta/sid/cp scan (4096 pts/block, grid 64x8) ----------------
// NO per-point histogram atomic here anymore (moved into pass_b packed atomic).
__global__ void __launch_bounds__(256) pass_a_kernel(
    const float* __restrict__ beta,
    const int* __restrict__ sid,
    const int* __restrict__ cp)
{
    const int b   = blockIdx.y;
    const int tid = threadIdx.x;

    __shared__ float s_f[KK];
    __shared__ int   s_cnt[KK];
    __shared__ int   s_first[KK];     // max(NN - li), 0 = none
    __shared__ float s_sc[4];
    __shared__ int   s_si[2];

    s_f[tid] = 0.f; s_cnt[tid] = 0; s_first[tid] = 0;
    if (tid < 4) s_sc[tid] = 0.f;
    if (tid < 2) s_si[tid] = 0;
    __syncthreads();

    float ce0n = 0.f, bg = 0.f, pm = 0.f, nm = 0.f;
    int ncp = 0, nbg = 0;

    const size_t ev_base = (size_t)b * NN;
    const int blk_base = blockIdx.x * 4096;

    for (int it = 0; it < 4; it++) {
        const int li0 = blk_base + it * 1024 + tid * 4;
        const int4   s4 = *reinterpret_cast<const int4*>(sid + ev_base + li0);
        const int4   c4 = *reinterpret_cast<const int4*>(cp  + ev_base + li0);
        const float4 x4 = *reinterpret_cast<const float4*>(beta + ev_base + li0);

        const int   sv[4] = {s4.x, s4.y, s4.z, s4.w};
        const int   cv[4] = {c4.x, c4.y, c4.z, c4.w};
        const float xv[4] = {x4.x, x4.y, x4.z, x4.w};

        #pragma unroll
        for (int j = 0; j < 4; j++) {
            const int   s = sv[j];
            const float x = xv[j];
            float p, ce0;
            fast_sig_sp(x, p, ce0);

            if (cv[j]) {
                ncp++;
                pm += fmaxf(0.8f - p, 0.f);
                if (s >= 0) {
                    const float om = 1.f - p;
                    atomicAdd(&s_f[s], 0.75f * om * om * (ce0 - x));
                    atomicAdd(&s_cnt[s], 1);
                    atomicMax(&s_first[s], NN - (li0 + j));
                    int pos = atomicAdd(&g_Mv[b], 1);
                    if (pos < CAP) g_cplist[b][pos] = li0 + j;
                }
            } else {
                ce0n += ce0;
                nm += fmaxf(p - 0.2f, 0.f);
            }
            if (s == -1) { nbg++; bg += ce0; }
        }
    }

    atomicAdd(&s_sc[0], ce0n);
    atomicAdd(&s_sc[1], bg);
    atomicAdd(&s_sc[2], pm);
    atomicAdd(&s_sc[3], nm);
    atomicAdd(&s_si[0], ncp);
    atomicAdd(&s_si[1], nbg);
    __syncthreads();

    if (s_f[tid] != 0.f) atomicAdd(&g_sum_f[b][tid], s_f[tid]);
    if (s_cnt[tid])      atomicAdd(&g_cnt_cp[b][tid], s_cnt[tid]);
    if (s_first[tid])    atomicMax(&g_first[b][tid], s_first[tid]);
    if (tid < 4) atomicAdd(&g_scal_f[b][tid], s_sc[tid]);
    if (tid < 2) atomicAdd(&g_scal_i[b][tid], s_si[tid]);
}

// ---------------- rep prep (+ anchor gather): one block per event ----------------
__global__ void __launch_bounds__(1024) rep_prep_kernel(const float* __restrict__ embed) {
    const int b   = blockIdx.x;
    const int tid = threadIdx.x;
    __shared__ int sidx[CAP];

    // anchor gather (independent of sidx work)
    for (int t = tid; t < KK * 4; t += 1024) {
        const int q = t & 3, k = t >> 2;
        const int val = g_first[b][k];
        float4 v = make_float4(0.f, 0.f, 0.f, 0.f);
        if (val > 0) {
            const int fi = NN - val;
            v = reinterpret_cast<const float4*>(embed + ((size_t)b * NN + fi) * DD)[q];
        }
        g_anchor[b][k][q] = v;
    }

    const int Mv   = g_Mv[b];
    const int mcol = min(Mv, CAP);
    const int msel = min(Mv, MMAX);

    for (int i = tid; i < CAP; i += 1024)
        sidx[i] = (i < mcol) ? g_cplist[b][i] : 0x7fffffff;
    __syncthreads();

    if (Mv > MMAX) {   // statistically never; correctness fallback
        for (int ksz = 2; ksz <= CAP; ksz <<= 1) {
            for (int j = ksz >> 1; j > 0; j >>= 1) {
                for (int i = tid; i < CAP; i += 1024) {
                    int ixj = i ^ j;
                    if (ixj > i) {
                        bool up = ((i & ksz) == 0);
                        int a = sidx[i], c = sidx[ixj];
                        if ((a > c) == up) { sidx[i] = c; sidx[ixj] = a; }
                    }
                }
                __syncthreads();
            }
        }
    }

    for (int t = tid; t < msel * 4; t += 1024) {
        const int i = t >> 2, qq = t & 3;
        g_cpemb[b][i * 4 + qq] =
            reinterpret_cast<const float4*>(embed + ((size_t)b * NN + sidx[i]) * DD)[qq];
    }
}

// ---------------- pass B: attraction + instance count, packed 64-bit atomic ----------
// 256 thr, grid (128, BB); thread handles 8 strided rows; sids prefetched (MLP).
// packed = (count << 44) | fixed_point_d2 (2^-20 scale).
__global__ void __launch_bounds__(256) pass_b_kernel(
    const float* __restrict__ embed,
    const int* __restrict__ sid)
{
    const int b   = blockIdx.y;
    const int tid = threadIdx.x;

    __shared__ float4             sA[KK][4];
    __shared__ unsigned long long spack[KK];
    __shared__ unsigned char      shc[KK];

    #pragma unroll
    for (int i = tid; i < KK * 4; i += 256)
        sA[i >> 2][i & 3] = g_anchor[b][i >> 2][i & 3];
    if (tid < KK) {
        spack[tid] = 0ull;
        shc[tid] = (g_cnt_cp[b][tid] > 0) ? 1 : 0;
    }
    __syncthreads();

    const size_t ev_base = (size_t)b * NN;
    const int base = blockIdx.x * 2048 + tid;

    int sv[8];
    #pragma unroll
    for (int r = 0; r < 8; r++)
        sv[r] = sid[ev_base + base + r * 256];

    #pragma unroll 2
    for (int r = 0; r < 8; r++) {
        const int s = sv[r];
        if (s >= 0) {
            unsigned long long pack = 1ull << 44;
            if (shc[s]) {
                const float4* e = reinterpret_cast<const float4*>(
                    embed + (ev_base + base + r * 256) * DD);
                const float4 e0 = e[0], e1 = e[1], e2 = e[2], e3 = e[3];
                const float4 a0 = sA[s][0], a1 = sA[s][1], a2 = sA[s][2], a3 = sA[s][3];
                float d2 = 0.f;
                d2 = __fmaf_rn(e0.x - a0.x, e0.x - a0.x, d2);
                d2 = __fmaf_rn(e0.y - a0.y, e0.y - a0.y, d2);
                d2 = __fmaf_rn(e0.z - a0.z, e0.z - a0.z, d2);
                d2 = __fmaf_rn(e0.w - a0.w, e0.w - a0.w, d2);
                d2 = __fmaf_rn(e1.x - a1.x, e1.x - a1.x, d2);
                d2 = __fmaf_rn(e1.y - a1.y, e1.y - a1.y, d2);
                d2 = __fmaf_rn(e1.z - a1.z, e1.z - a1.z, d2);
                d2 = __fmaf_rn(e1.w - a1.w, e1.w - a1.w, d2);
                d2 = __fmaf_rn(e2.x - a2.x, e2.x - a2.x, d2);
                d2 = __fmaf_rn(e2.y - a2.y, e2.y - a2.y, d2);
                d2 = __fmaf_rn(e2.z - a2.z, e2.z - a2.z, d2);
                d2 = __fmaf_rn(e2.w - a2.w, e2.w - a2.w, d2);
                d2 = __fmaf_rn(e3.x - a3.x, e3.x - a3.x, d2);
                d2 = __fmaf_rn(e3.y - a3.y, e3.y - a3.y, d2);
                d2 = __fmaf_rn(e3.z - a3.z, e3.z - a3.z, d2);
                d2 = __fmaf_rn(e3.w - a3.w, e3.w - a3.w, d2);
                pack += __float2ull_rn(d2 * 1048576.f);
            }
            atomicAdd(&spack[s], pack);
        }
    }
    __syncthreads();
    if (tid < KK) {
        const unsigned long long v = spack[tid];
        if (v) {
            atomicAdd(&g_inst[b][tid], (int)(v >> 44));
            const float ds = (float)(v & ((1ull << 44) - 1ull)) * (1.f / 1048576.f);
            if (ds != 0.f) atomicAdd(&g_sd2[b][tid], ds);
        }
    }
}

// ---------------- repulsion compute: grid (16 j-chunks, BB), 256 thr ----------------
#define RCH 64
__global__ void __launch_bounds__(256) rep_compute_kernel() {
    const int b   = blockIdx.y;
    const int tid = threadIdx.x;
    const int j0  = blockIdx.x * RCH;

    const int Mv   = g_Mv[b];
    const int msel = min(Mv, MMAX);
    if (j0 >= msel) return;
    const int cnt = min(RCH, msel - j0);

    __shared__ float sj[RCH * DD];
    __shared__ float red[8];

    for (int t = tid; t < cnt * 4; t += 256) {
        const int j = t >> 2, qq = t & 3;
        reinterpret_cast<float4*>(sj)[j * 4 + qq] = g_cpemb[b][(j0 + j) * 4 + qq];
    }
    __syncthreads();

    float acc = 0.f;
    for (int i = tid; i < msel; i += 256) {
        float myE[DD];
        #pragma unroll
        for (int qq = 0; qq < 4; qq++) {
            const float4 v = g_cpemb[b][i * 4 + qq];
            myE[qq * 4 + 0] = v.x; myE[qq * 4 + 1] = v.y;
            myE[qq * 4 + 2] = v.z; myE[qq * 4 + 3] = v.w;
        }
        for (int j = 0; j < cnt; j++) {
            float d2 = 0.f;
            #pragma unroll
            for (int d = 0; d < DD; d++) {
                const float df = myE[d] - sj[j * DD + d];
                d2 = __fmaf_rn(df, df, d2);
            }
            acc += __expf(-d2);
        }
    }

    #pragma unroll
    for (int off = 16; off; off >>= 1) acc += __shfl_down_sync(0xffffffff, acc, off);
    if ((tid & 31) == 0) red[tid >> 5] = acc;
    __syncthreads();
    if (tid == 0) {
        float tot = 0.f;
        #pragma unroll
        for (int w = 0; w < 8; w++) tot += red[w];
        atomicAdd(&g_rep[b], tot);
    }
}

// ---------------- finalize (+ state reset for graph replay) ----------------
__global__ void __launch_bounds__(256) finalize_kernel(float* __restrict__ out) {
    const int tid  = threadIdx.x;
    const int lane = tid & 31;
    const int wid  = tid >> 5;
    __shared__ float rw[8], rwf[8], rat[8];
    __shared__ float s_total[1], s_cnt[1];
    if (tid == 0) { s_total[0] = 0.f; s_cnt[0] = 0.f; }
    __syncthreads();

    for (int b = 0; b < BB; b++) {
        const int c    = g_cnt_cp[b][tid];
        const int inst = g_inst[b][tid];
        float w = 0.f, wf = 0.f, at = 0.f;
        if (c > 0) {
            w  = (float)inst;
            wf = w * g_sum_f[b][tid] / fmaxf((float)c, 1.f);
            at = g_sd2[b][tid] / fmaxf((float)inst, 1.f);
        }
        #pragma unroll
        for (int off = 16; off; off >>= 1) {
            w  += __shfl_down_sync(0xffffffff, w,  off);
            wf += __shfl_down_sync(0xffffffff, wf, off);
            at += __shfl_down_sync(0xffffffff, at, off);
        }
        if (lane == 0) { rw[wid] = w; rwf[wid] = wf; rat[wid] = at; }
        __syncthreads();
        if (tid == 0) {
            float sw = 0.f, swf = 0.f, sat = 0.f;
            for (int qq = 0; qq < 8; qq++) { sw += rw[qq]; swf += rwf[qq]; sat += rat[qq]; }
            const float pos_bce = swf / fmaxf(sw, 1.f);

            const float n_cp  = (float)g_scal_i[b][0];
            const float n_bg  = (float)g_scal_i[b][1];
            const float n_ncp = (float)NN - n_cp;
            const float n_val = (float)NN - n_bg;

            const float neg_bce    = (n_ncp > 0.f) ? g_scal_f[b][0] / fmaxf(n_ncp, 1.f) : 0.f;
            const float bg_bce     = (n_bg  > 0.f) ? g_scal_f[b][1] / fmaxf(n_bg,  1.f) : 0.f;
            const float pos_margin = g_scal_f[b][2] / fmaxf(n_cp, 1.f);
            const float neg_margin = (n_ncp > 0.f) ? g_scal_f[b][3] / fmaxf(n_ncp, 1.f) : 0.f;

            const float beta_loss = 10.f * pos_bce + 3.f * neg_bce + 6.f * bg_bce
                                  + 10.f * (pos_margin + neg_margin);

            const int   Mv = g_Mv[b];
            const float fM = (float)Mv;
            const float rep_term = (Mv > 1) ? g_rep[b] / fmaxf(fM * fM, 1.f) : 0.f;

            const float loss = beta_loss + sat + rep_term;

            const bool ok = (n_val > 0.f) && (Mv > 0);
            if (ok) { s_total[0] += loss; s_cnt[0] += 1.f; }
        }
        __syncthreads();
    }
    if (tid == 0)
        out[0] = (s_cnt[0] > 0.f) ? s_total[0] / fmaxf(s_cnt[0], 1.f) : 0.f;

    // reset all scratch to zero-state so the graph replays deterministically
    __syncthreads();
    #pragma unroll
    for (int b = 0; b < BB; b++) {
        g_sum_f[b][tid]  = 0.f;
        g_cnt_cp[b][tid] = 0;
        g_inst[b][tid]   = 0;
        g_first[b][tid]  = 0;
        g_sd2[b][tid]    = 0.f;
    }
    if (tid < BB) {
        g_Mv[tid]  = 0;
        g_rep[tid] = 0.f;
        #pragma unroll
        for (int j = 0; j < 4; j++) g_scal_f[tid][j] = 0.f;
        g_scal_i[tid][0] = 0; g_scal_i[tid][1] = 0;
    }
}

// ---------------- launch ----------------
extern "C" void kernel_launch(void* const* d_in, const int* in_sizes, int n_in,
                              void* d_out, int out_size)
{
    (void)in_sizes; (void)n_in; (void)out_size;
    const float* beta  = (const float*)d_in[0];
    const float* embed = (const float*)d_in[1];
    const int*   sid   = (const int*)d_in[2];
    const int*   cp    = (const int*)d_in[3];

    pass_a_kernel<<<dim3(64, BB), 256>>>(beta, sid, cp);
    rep_prep_kernel<<<BB, 1024>>>(embed);
    pass_b_kernel<<<dim3(128, BB), 256>>>(embed, sid);
    rep_compute_kernel<<<dim3(16, BB), 256>>>();
    finalize_kernel<<<1, 256>>>((float*)d_out);
}